// round 8
// baseline (speedup 1.0000x reference)
#include <cuda_runtime.h>
#include <math.h>
#include <stdint.h>

#define BSZ   8192
#define NBLK  8
#define HDIM  256
#define DDIM  256
#define DKIN  16
#define DVIN  32
#define NHC   4
#define KACT  4

// ---------------- device scratch ----------------
__device__ float g_mask  [BSZ * NBLK];
__device__ float g_inputs[BSZ * NBLK * DVIN];
__device__ float g_hsnew [BSZ * NBLK * HDIM];
__device__ float g_q2    [BSZ * NBLK * 32];
__device__ float g_k2    [BSZ * NBLK * 32];
__device__ float g_v2    [BSZ * NBLK * 1024];
__device__ float g_ctx   [BSZ * NBLK * 1024];
__device__ float g_kv    [BSZ * 2 * 48];
__device__ float g_ql    [BSZ * NBLK * 16];

// ---------------- helpers (arch-agnostic PTX, sm_80+) ----------------
__device__ __forceinline__ uint32_t smem_u32(const void* p) {
    uint32_t a;
    asm("{ .reg .u64 t; cvta.to.shared.u64 t, %1; cvt.u32.u64 %0, t; }" : "=r"(a) : "l"(p));
    return a;
}
#define CPA16(dst, src) asm volatile("cp.async.cg.shared.global [%0], [%1], 16;" :: "r"(dst), "l"(src))
#define CPCOMMIT()      asm volatile("cp.async.commit_group;" ::: "memory")
#define CPWAIT1()       asm volatile("cp.async.wait_group 1;" ::: "memory")
#define CPWAIT0()       asm volatile("cp.async.wait_group 0;" ::: "memory")

__device__ __forceinline__ void mma8(float* d, uint32_t a0, uint32_t a1, uint32_t a2,
                                     uint32_t a3, uint32_t b0, uint32_t b1) {
    asm volatile("mma.sync.aligned.m16n8k8.row.col.f32.tf32.tf32.f32 "
        "{%0,%1,%2,%3}, {%4,%5,%6,%7}, {%8,%9}, {%0,%1,%2,%3};"
        : "+f"(d[0]), "+f"(d[1]), "+f"(d[2]), "+f"(d[3])
        : "r"(a0), "r"(a1), "r"(a2), "r"(a3), "r"(b0), "r"(b1));
}
__device__ __forceinline__ float sigf(float x) { return 1.f / (1.f + expf(-x)); }
__device__ __forceinline__ uint32_t fu(float x) { return __float_as_uint(x); }

// 32x32-warp-tile MMA step (A stride 36, B stride 72), accumulators acc[2][4][4]
#define MMA_32x32(A_, B_) \
    _Pragma("unroll") for (int ks = 0; ks < 4; ks++) { \
        int k0 = ks * 8; \
        uint32_t a[2][4]; \
        _Pragma("unroll") for (int mi = 0; mi < 2; mi++) { \
            const float* ap = &(A_)[(wm * 32 + mi * 16 + lr) * 36 + k0 + lc]; \
            a[mi][0] = fu(ap[0]); a[mi][1] = fu(ap[288]); \
            a[mi][2] = fu(ap[4]); a[mi][3] = fu(ap[292]); } \
        _Pragma("unroll") for (int ni = 0; ni < 4; ni++) { \
            int col = wn * 32 + ni * 8 + lr; \
            uint32_t b0f = fu((B_)[(k0 + lc) * 72 + col]); \
            uint32_t b1f = fu((B_)[(k0 + lc + 4) * 72 + col]); \
            mma8(acc[0][ni], a[0][0], a[0][1], a[0][2], a[0][3], b0f, b1f); \
            mma8(acc[1][ni], a[1][0], a[1][1], a[1][2], a[1][3], b0f, b1f); } }

// ================= k1a_kv: [kL|vL] = x @ [Wkey|Wval]  (16384 x 48, K=256) =
__global__ __launch_bounds__(256) void k1a_kv(
    const float* __restrict__ x1, const float* __restrict__ x2,
    const float* __restrict__ Wkey, const float* __restrict__ Wval)
{
    extern __shared__ float sm[];
    float* sA = sm;             // 2 * 4608
    float* sB = sm + 2 * 4608;  // 2 * 1792 (32 x 56)
    uint32_t aB = smem_u32(sA), bB = smem_u32(sB);
    const int b0 = blockIdx.x * 128;
    const int tid = threadIdx.x, warp = tid >> 5, lane = tid & 31;
    const int wm = warp >> 1, wn = warp & 1;
    const int lr = lane >> 2, lc = lane & 3;
    float acc[2][3][4] = {};

#define KV_ISSUE(kt, st) { \
    for (int l = tid; l < 1024; l += 256) { int r = l >> 3, k4 = l & 7; \
        int row = b0 + r; const float* src = ((row & 1) ? x2 : x1) + (row >> 1) * 256 + (kt) * 32 + k4 * 4; \
        CPA16(aB + ((st) * 4608 + r * 36 + k4 * 4) * 4, src); } \
    for (int l = tid; l < 384; l += 256) { int k = l / 12, c4 = l % 12; int c = c4 * 4; \
        const float* src = (c < 16) ? &Wkey[((kt) * 32 + k) * 16 + c] : &Wval[((kt) * 32 + k) * 32 + c - 16]; \
        CPA16(bB + ((st) * 1792 + k * 56 + c) * 4, src); } \
    CPCOMMIT(); }

    KV_ISSUE(0, 0);
    for (int kt = 0; kt < 8; kt++) {
        if (kt < 7) { KV_ISSUE(kt + 1, (kt + 1) & 1); CPWAIT1(); }
        else CPWAIT0();
        __syncthreads();
        const float* A_ = sA + (kt & 1) * 4608;
        const float* B_ = sB + (kt & 1) * 1792;
        #pragma unroll
        for (int ks = 0; ks < 4; ks++) {
            int k0 = ks * 8;
            uint32_t a[2][4];
            #pragma unroll
            for (int mi = 0; mi < 2; mi++) {
                const float* ap = &A_[(wm * 32 + mi * 16 + lr) * 36 + k0 + lc];
                a[mi][0] = fu(ap[0]); a[mi][1] = fu(ap[288]);
                a[mi][2] = fu(ap[4]); a[mi][3] = fu(ap[292]);
            }
            #pragma unroll
            for (int ni = 0; ni < 3; ni++) {
                int col = wn * 24 + ni * 8 + lr;
                uint32_t b0f = fu(B_[(k0 + lc) * 56 + col]);
                uint32_t b1f = fu(B_[(k0 + lc + 4) * 56 + col]);
                mma8(acc[0][ni], a[0][0], a[0][1], a[0][2], a[0][3], b0f, b1f);
                mma8(acc[1][ni], a[1][0], a[1][1], a[1][2], a[1][3], b0f, b1f);
            }
        }
        __syncthreads();
    }
    #pragma unroll
    for (int mi = 0; mi < 2; mi++)
        #pragma unroll
        for (int ni = 0; ni < 3; ni++) {
            int col = wn * 24 + ni * 8 + 2 * lc;
            int r0 = b0 + wm * 32 + mi * 16 + lr;
            *(float2*)&g_kv[r0 * 48 + col]       = make_float2(acc[mi][ni][0], acc[mi][ni][1]);
            *(float2*)&g_kv[(r0 + 8) * 48 + col] = make_float2(acc[mi][ni][2], acc[mi][ni][3]);
        }
}

// ================= k1a_ql: qL = hs @ Wq[n]  (8192 x 16 per n, K=256) =====
__global__ __launch_bounds__(256) void k1a_ql(
    const float* __restrict__ hs, const float* __restrict__ Wq)
{
    extern __shared__ float sm[];
    float* sA = sm;             // 2 * 4608
    float* sB = sm + 2 * 4608;  // 2 * 768 (32 x 24)
    uint32_t aB = smem_u32(sA), bB = smem_u32(sB);
    const int n = blockIdx.y, b0 = blockIdx.x * 128;
    const int tid = threadIdx.x, warp = tid >> 5, lane = tid & 31;
    const int wm = warp;
    const int lr = lane >> 2, lc = lane & 3;
    float acc[2][4] = {};

#define QL_ISSUE(kt, st) { \
    for (int l = tid; l < 1024; l += 256) { int r = l >> 3, k4 = l & 7; \
        CPA16(aB + ((st) * 4608 + r * 36 + k4 * 4) * 4, \
              &hs[((b0 + r) * NBLK + n) * 256 + (kt) * 32 + k4 * 4]); } \
    for (int l = tid; l < 128; l += 256) { int k = l >> 2, c4 = l & 3; \
        CPA16(bB + ((st) * 768 + k * 24 + c4 * 4) * 4, \
              &Wq[(n * 256 + (kt) * 32 + k) * 16 + c4 * 4]); } \
    CPCOMMIT(); }

    QL_ISSUE(0, 0);
    for (int kt = 0; kt < 8; kt++) {
        if (kt < 7) { QL_ISSUE(kt + 1, (kt + 1) & 1); CPWAIT1(); }
        else CPWAIT0();
        __syncthreads();
        const float* A_ = sA + (kt & 1) * 4608;
        const float* B_ = sB + (kt & 1) * 768;
        #pragma unroll
        for (int ks = 0; ks < 4; ks++) {
            int k0 = ks * 8;
            const float* ap = &A_[(wm * 16 + lr) * 36 + k0 + lc];
            uint32_t a0 = fu(ap[0]), a1 = fu(ap[288]), a2 = fu(ap[4]), a3 = fu(ap[292]);
            #pragma unroll
            for (int ni = 0; ni < 2; ni++) {
                int col = ni * 8 + lr;
                uint32_t b0f = fu(B_[(k0 + lc) * 24 + col]);
                uint32_t b1f = fu(B_[(k0 + lc + 4) * 24 + col]);
                mma8(acc[ni], a0, a1, a2, a3, b0f, b1f);
            }
        }
        __syncthreads();
    }
    #pragma unroll
    for (int ni = 0; ni < 2; ni++) {
        int col = ni * 8 + 2 * lc;
        int r0 = b0 + wm * 16 + lr;
        *(float2*)&g_ql[(r0 * NBLK + n) * 16 + col]       = make_float2(acc[ni][0], acc[ni][1]);
        *(float2*)&g_ql[((r0 + 8) * NBLK + n) * 16 + col] = make_float2(acc[ni][2], acc[ni][3]);
    }
}

// ================= k1b: scores, top-k mask, softmax, inputs ==============
__global__ __launch_bounds__(256) void k1b_gate(
    const float* __restrict__ bkey, const float* __restrict__ bval)
{
    const int w = threadIdx.x >> 5, lane = threadIdx.x & 31;
    const int b = blockIdx.x * 8 + w;

    __shared__ float sKL[8][48];
    __shared__ float sVL[8][96];
    __shared__ float sQL[8][128];
    __shared__ float sS [8][24];
    __shared__ float sM [8][8];

    for (int o = lane; o < 48; o += 32) {
        int s = o >> 4, j = o & 15;
        sKL[w][o] = bkey[j] + (s < 2 ? g_kv[(b * 2 + s) * 48 + j] : 0.f);
    }
    for (int o = lane; o < 96; o += 32) {
        int s = o >> 5, j = o & 31;
        sVL[w][o] = bval[j] + (s < 2 ? g_kv[(b * 2 + s) * 48 + 16 + j] : 0.f);
    }
    for (int o = lane; o < 128; o += 32) sQL[w][o] = g_ql[b * 128 + o];
    __syncwarp();

    for (int o = lane; o < 24; o += 32) {
        int nn = o / 3, s = o % 3;
        float acc = 0.f;
        #pragma unroll
        for (int j = 0; j < 16; j++) acc += sQL[w][nn * 16 + j] * sKL[w][s * 16 + j];
        sS[w][o] = acc * 0.25f;
    }
    __syncwarp();

    if (lane < 8) {
        float nu = sS[w][lane * 3 + 2];
        int rank = 0;
        #pragma unroll
        for (int n2 = 0; n2 < 8; n2++) {
            float nu2 = sS[w][n2 * 3 + 2];
            rank += (nu2 > nu) || (nu2 == nu && n2 < lane);
        }
        float m = (rank < (NBLK - KACT)) ? 0.f : 1.f;
        sM[w][lane] = m;
        g_mask[b * NBLK + lane] = m;
    }
    __syncwarp();

    for (int o = lane; o < 256; o += 32) {
        int nn = o >> 5, j = o & 31;
        float s0 = sS[w][nn * 3 + 0], s1 = sS[w][nn * 3 + 1], s2 = sS[w][nn * 3 + 2];
        float mx = fmaxf(s0, fmaxf(s1, s2));
        float e0 = expf(s0 - mx), e1 = expf(s1 - mx), e2 = expf(s2 - mx);
        float inv = 1.f / (e0 + e1 + e2);
        float val = (e0 * sVL[w][j] + e1 * sVL[w][32 + j] + e2 * sVL[w][64 + j])
                    * inv * sM[w][nn];
        g_inputs[(b * NBLK + nn) * DVIN + j] = val;
    }
}

// ================= k2: fused GRU, combined r/z accumulators ==============
// grid (64, 16, 8); 128 rows x 16h x 3 gates; hoisted cp.async addressing
__global__ __launch_bounds__(256) void k2_gru(
    const float* __restrict__ hs,
    const float* __restrict__ Wx2h,
    const float* __restrict__ Wh2h)
{
    extern __shared__ float sm[];
    float* sA = sm;             // 2 * 4608
    float* sB = sm + 2 * 4608;  // 2 * 1792 (32 x 56)
    uint32_t aB = smem_u32(sA), bB = smem_u32(sB);
    const int n = blockIdx.z, b0 = blockIdx.x * 128, h0 = blockIdx.y * 16;
    const int tid = threadIdx.x, warp = tid >> 5, lane = tid & 31;
    const int wm = warp >> 1, wn = warp & 1;
    const int lr = lane >> 2, lc = lane & 3;

    float arz[2][2][4] = {};   // r,z: accumulate gate_x AND gate_h
    float anx[2][4] = {};      // i_n (phase 1)
    float anh[2][4] = {};      // h_n (phase 2)

#define K2_MMA(A_, B_, NACC) \
    _Pragma("unroll") for (int ks = 0; ks < 4; ks++) { \
        int k0 = ks * 8; \
        uint32_t a[2][4]; \
        _Pragma("unroll") for (int mi = 0; mi < 2; mi++) { \
            const float* ap = &(A_)[(wm * 32 + mi * 16 + lr) * 36 + k0 + lc]; \
            a[mi][0] = fu(ap[0]); a[mi][1] = fu(ap[288]); \
            a[mi][2] = fu(ap[4]); a[mi][3] = fu(ap[292]); } \
        _Pragma("unroll") for (int g = 0; g < 3; g++) { \
            int col = g * 16 + wn * 8 + lr; \
            uint32_t b0f = fu((B_)[(k0 + lc) * 56 + col]); \
            uint32_t b1f = fu((B_)[(k0 + lc + 4) * 56 + col]); \
            float* d0 = (g < 2) ? arz[0][g] : NACC[0]; \
            float* d1 = (g < 2) ? arz[1][g] : NACC[1]; \
            mma8(d0, a[0][0], a[0][1], a[0][2], a[0][3], b0f, b1f); \
            mma8(d1, a[1][0], a[1][1], a[1][2], a[1][3], b0f, b1f); } }

    // hoisted per-thread cp.async addressing (phase 2)
    const int rb = tid >> 3, k4 = tid & 7;
    const float* srcA[4];
    uint32_t dstA[4];
    #pragma unroll
    for (int i = 0; i < 4; i++) {
        int r = rb + 32 * i;
        srcA[i] = &hs[((b0 + r) * NBLK + n) * 256 + k4 * 4];
        dstA[i] = aB + (r * 36 + k4 * 4) * 4;
    }
    const int kB = tid / 12, c4B = tid % 12;     // only tid<384 -> tid<256 all valid? 384>256: iter0 valid for all, iter1 tid<128
    const int gB = c4B >> 2, ccB = c4B & 3;
    const float* srcB0 = &Wh2h[(n * 256 + kB) * 768 + gB * 256 + h0 + ccB * 4];
    uint32_t dstB0 = bB + (kB * 56 + gB * 16 + ccB * 4) * 4;
    const int l1 = tid + 256;
    const int kB1 = l1 / 12, c4B1 = l1 % 12, gB1 = c4B1 >> 2, ccB1 = c4B1 & 3;
    const float* srcB1 = (tid < 128) ? &Wh2h[(n * 256 + kB1) * 768 + gB1 * 256 + h0 + ccB1 * 4] : 0;
    uint32_t dstB1 = bB + (kB1 * 56 + gB1 * 16 + ccB1 * 4) * 4;

#define K2_ISSUE(kt, st) { \
    _Pragma("unroll") for (int i = 0; i < 4; i++) \
        CPA16(dstA[i] + (st) * 4608 * 4, srcA[i] + (kt) * 32); \
    CPA16(dstB0 + (st) * 1792 * 4, srcB0 + (kt) * 32 * 768); \
    if (tid < 128) CPA16(dstB1 + (st) * 1792 * 4, srcB1 + (kt) * 32 * 768); \
    CPCOMMIT(); }

    // phase 1: gate_x (K=32, one tile, stage 0)
    for (int l = tid; l < 1024; l += 256) {
        int r = l >> 3, kk4 = l & 7;
        CPA16(aB + (r * 36 + kk4 * 4) * 4, &g_inputs[((b0 + r) * NBLK + n) * 32 + kk4 * 4]);
    }
    {
        CPA16(dstB0, &Wx2h[(n * 32 + kB) * 768 + gB * 256 + h0 + ccB * 4]);
        if (tid < 128) CPA16(dstB1, &Wx2h[(n * 32 + kB1) * 768 + gB1 * 256 + h0 + ccB1 * 4]);
    }
    CPCOMMIT(); CPWAIT0();
    __syncthreads();
    K2_MMA(sA, sB, anx);
    __syncthreads();

    // phase 2: gate_h (K=256, 8 K-tiles, double-buffered)
    K2_ISSUE(0, 0);
    for (int kt = 0; kt < 8; kt++) {
        if (kt < 7) { K2_ISSUE(kt + 1, (kt + 1) & 1); CPWAIT1(); }
        else CPWAIT0();
        __syncthreads();
        const float* A_ = sA + (kt & 1) * 4608;
        const float* B_ = sB + (kt & 1) * 1792;
        K2_MMA(A_, B_, anh);
        __syncthreads();
    }

    // epilogue
    #pragma unroll
    for (int mi = 0; mi < 2; mi++)
        #pragma unroll
        for (int half = 0; half < 2; half++) {
            int row = b0 + wm * 32 + mi * 16 + lr + half * 8;
            int idx = (row * NBLK + n) * HDIM + h0 + wn * 8 + 2 * lc;
            float2 hold = *(const float2*)&hs[idx];
            int e = half * 2;
            float r0 = sigf(arz[mi][0][e + 0]);
            float r1 = sigf(arz[mi][0][e + 1]);
            float z0 = sigf(arz[mi][1][e + 0]);
            float z1 = sigf(arz[mi][1][e + 1]);
            float n0 = tanhf(anx[mi][e + 0] + r0 * anh[mi][e + 0]);
            float n1 = tanhf(anx[mi][e + 1] + r1 * anh[mi][e + 1]);
            float2 o;
            o.x = n0 + z0 * (hold.x - n0);
            o.y = n1 + z1 * (hold.y - n1);
            *(float2*)&g_hsnew[idx] = o;
        }
}

// ========== k3b fused: v2 = hs_new @ Wv_  AND  [q2|k2] = hs_new @ [Wq_|Wk_]
// grid (64, 17, 8): y<16 -> Wv_ col-tile y; y==16 -> qk tile. K=256.
__global__ __launch_bounds__(256) void k3b_v2qk(
    const float* __restrict__ Wv_,
    const float* __restrict__ Wq_, const float* __restrict__ Wk_)
{
    extern __shared__ float sm[];
    float* sAx = sm;             // 2 * 4608
    float* sBx = sm + 2 * 4608;  // 2 * 2304
    uint32_t aB = smem_u32(sAx), bB = smem_u32(sBx);
    const int n = blockIdx.z, b0 = blockIdx.x * 128;
    const int oy = blockIdx.y;
    const bool isqk = (oy == 16);
    const int o0 = oy * 64;
    const int tid = threadIdx.x, warp = tid >> 5, lane = tid & 31;
    const int wm = warp >> 1, wn = warp & 1;
    const int lr = lane >> 2, lc = lane & 3;
    float acc[2][4][4] = {};

    // hoisted addressing
    const int rb = tid >> 3, k4 = tid & 7;
    const float* srcA[4];
    uint32_t dstA[4];
    #pragma unroll
    for (int i = 0; i < 4; i++) {
        int r = rb + 32 * i;
        srcA[i] = &g_hsnew[((b0 + r) * NBLK + n) * 256 + k4 * 4];
        dstA[i] = aB + (r * 36 + k4 * 4) * 4;
    }
    const int kBb = tid >> 4, c4 = tid & 15;
    const float* srcB[2];
    uint32_t dstB[2];
    long strB;
    #pragma unroll
    for (int i = 0; i < 2; i++) {
        int k = kBb + 16 * i;
        if (!isqk) srcB[i] = &Wv_[(n * 256 + k) * 1024 + o0 + c4 * 4];
        else srcB[i] = (c4 < 8) ? &Wq_[(n * 256 + k) * 32 + c4 * 4]
                                : &Wk_[(n * 256 + k) * 32 + (c4 - 8) * 4];
        dstB[i] = bB + (k * 72 + c4 * 4) * 4;
    }
    strB = isqk ? (32 * 32) : (32 * 1024);

#define K3B_ISSUE(kt, st) { \
    _Pragma("unroll") for (int i = 0; i < 4; i++) \
        CPA16(dstA[i] + (st) * 4608 * 4, srcA[i] + (kt) * 32); \
    _Pragma("unroll") for (int i = 0; i < 2; i++) \
        CPA16(dstB[i] + (st) * 2304 * 4, srcB[i] + (kt) * strB); \
    CPCOMMIT(); }

    K3B_ISSUE(0, 0);
    for (int kt = 0; kt < 8; kt++) {
        if (kt < 7) { K3B_ISSUE(kt + 1, (kt + 1) & 1); CPWAIT1(); }
        else CPWAIT0();
        __syncthreads();
        const float* A_ = sAx + (kt & 1) * 4608;
        const float* B_ = sBx + (kt & 1) * 2304;
        MMA_32x32(A_, B_);
        __syncthreads();
    }
    if (!isqk) {
        #pragma unroll
        for (int mi = 0; mi < 2; mi++)
            #pragma unroll
            for (int ni = 0; ni < 4; ni++) {
                int col = o0 + wn * 32 + ni * 8 + 2 * lc;
                int r0 = b0 + wm * 32 + mi * 16 + lr;
                *(float2*)&g_v2[(r0 * NBLK + n) * 1024 + col]       = make_float2(acc[mi][ni][0], acc[mi][ni][1]);
                *(float2*)&g_v2[((r0 + 8) * NBLK + n) * 1024 + col] = make_float2(acc[mi][ni][2], acc[mi][ni][3]);
            }
    } else {
        #pragma unroll
        for (int mi = 0; mi < 2; mi++)
            #pragma unroll
            for (int ni = 0; ni < 4; ni++) {
                int col = wn * 32 + ni * 8 + 2 * lc;
                float* dst = (col < 32) ? g_q2 : g_k2;
                int cc = col & 31;
                int r0 = b0 + wm * 32 + mi * 16 + lr;
                *(float2*)&dst[(r0 * NBLK + n) * 32 + cc]       = make_float2(acc[mi][ni][0], acc[mi][ni][1]);
                *(float2*)&dst[((r0 + 8) * NBLK + n) * 32 + cc] = make_float2(acc[mi][ni][2], acc[mi][ni][3]);
            }
    }
}

// ================= k3c: fused attention + ctx = att @ v2 =================
__global__ __launch_bounds__(256) void k3c_ctx()
{
    const int b = blockIdx.x;
    __shared__ float4 sV[2048];
    __shared__ float sQ[256], sK[256], sAtt[256];

    const float4* vb = (const float4*)(g_v2 + b * 8192);
    for (int l = threadIdx.x; l < 2048; l += 256) sV[l] = vb[l];
    sQ[threadIdx.x] = g_q2[b * 256 + threadIdx.x];
    sK[threadIdx.x] = g_k2[b * 256 + threadIdx.x];
    __syncthreads();

    if (threadIdx.x < 32) {
        const int lane = threadIdx.x;
        const int h = lane >> 3, nq = lane & 7;
        float sc[8], mx = -1e30f;
        #pragma unroll
        for (int m = 0; m < 8; m++) {
            float s = 0.f;
            #pragma unroll
            for (int dk = 0; dk < 8; dk++)
                s += sQ[nq * 32 + h * 8 + dk] * sK[m * 32 + h * 8 + dk];
            s *= 0.35355339059327373f;
            sc[m] = s;
            mx = fmaxf(mx, s);
        }
        float den = 0.f;
        #pragma unroll
        for (int m = 0; m < 8; m++) { sc[m] = expf(sc[m] - mx); den += sc[m]; }
        float scale = g_mask[b * NBLK + nq] / den;
        #pragma unroll
        for (int m = 0; m < 8; m++)
            sAtt[(h * 8 + nq) * 8 + m] = sc[m] * scale;
    }
    __syncthreads();

    float4* cb = (float4*)(g_ctx + b * 8192);
    for (int l = threadIdx.x; l < 2048; l += 256) {
        int nq = l >> 8, c4 = l & 255, g = c4 >> 6;
        const float* ap = &sAtt[(g * 8 + nq) * 8];
        float4 acc = make_float4(0.f, 0.f, 0.f, 0.f);
        #pragma unroll
        for (int m = 0; m < 8; m++) {
            float a = ap[m];
            float4 v = sV[m * 256 + c4];
            acc.x += a * v.x; acc.y += a * v.y; acc.z += a * v.z; acc.w += a * v.w;
        }
        cb[l] = acc;
    }
}

// ================= k3d: out = mask*(ctx@Wout + hs_new) + (1-m)*hs ========
__global__ __launch_bounds__(256) void k3d_out(
    const float* __restrict__ Wout, const float* __restrict__ hs,
    float* __restrict__ out)
{
    extern __shared__ float sm[];
    float* sAx = sm;
    float* sBx = sm + 2 * 4608;
    uint32_t aB = smem_u32(sAx), bB = smem_u32(sBx);
    const int n = blockIdx.z, b0 = blockIdx.x * 128, o0 = blockIdx.y * 64;
    const int tid = threadIdx.x, warp = tid >> 5, lane = tid & 31;
    const int wm = warp >> 1, wn = warp & 1;
    const int lr = lane >> 2, lc = lane & 3;
    float acc[2][4][4] = {};

    const int rb = tid >> 3, k4 = tid & 7;
    const float* srcA[4];
    uint32_t dstA[4];
    #pragma unroll
    for (int i = 0; i < 4; i++) {
        int r = rb + 32 * i;
        srcA[i] = &g_ctx[((b0 + r) * NBLK + n) * 1024 + k4 * 4];
        dstA[i] = aB + (r * 36 + k4 * 4) * 4;
    }
    const int kBb = tid >> 4, c4 = tid & 15;
    const float* srcB[2];
    uint32_t dstB[2];
    #pragma unroll
    for (int i = 0; i < 2; i++) {
        int k = kBb + 16 * i;
        srcB[i] = &Wout[(n * 1024 + k) * 256 + o0 + c4 * 4];
        dstB[i] = bB + (k * 72 + c4 * 4) * 4;
    }

#define K3D_ISSUE(kt, st) { \
    _Pragma("unroll") for (int i = 0; i < 4; i++) \
        CPA16(dstA[i] + (st) * 4608 * 4, srcA[i] + (kt) * 32); \
    _Pragma("unroll") for (int i = 0; i < 2; i++) \
        CPA16(dstB[i] + (st) * 2304 * 4, srcB[i] + (kt) * 32 * 256); \
    CPCOMMIT(); }

    K3D_ISSUE(0, 0);
    for (int kt = 0; kt < 32; kt++) {
        if (kt < 31) { K3D_ISSUE(kt + 1, (kt + 1) & 1); CPWAIT1(); }
        else CPWAIT0();
        __syncthreads();
        const float* A_ = sAx + (kt & 1) * 4608;
        const float* B_ = sBx + (kt & 1) * 2304;
        MMA_32x32(A_, B_);
        __syncthreads();
    }
    #pragma unroll
    for (int mi = 0; mi < 2; mi++)
        #pragma unroll
        for (int ni = 0; ni < 4; ni++) {
            int col = o0 + wn * 32 + ni * 8 + 2 * lc;
            #pragma unroll
            for (int half = 0; half < 2; half++) {
                int row = b0 + wm * 32 + mi * 16 + lr + half * 8;
                float m = g_mask[row * NBLK + n];
                int idx = (row * NBLK + n) * HDIM + col;
                float2 hn = *(const float2*)&g_hsnew[idx];
                float2 ho = *(const float2*)&hs[idx];
                float2 r;
                r.x = m * (acc[mi][ni][half * 2]     + hn.x) + (1.f - m) * ho.x;
                r.y = m * (acc[mi][ni][half * 2 + 1] + hn.y) + (1.f - m) * ho.y;
                *(float2*)&out[idx] = r;
            }
        }
}

// =========================== launch ======================================
extern "C" void kernel_launch(void* const* d_in, const int* in_sizes, int n_in,
                              void* d_out, int out_size)
{
    const float* x1   = (const float*)d_in[0];
    const float* x2   = (const float*)d_in[1];
    const float* hs   = (const float*)d_in[2];
    const float* Wkey = (const float*)d_in[3];
    const float* bkey = (const float*)d_in[4];
    const float* Wval = (const float*)d_in[5];
    const float* bval = (const float*)d_in[6];
    const float* Wq   = (const float*)d_in[7];
    const float* Wq_  = (const float*)d_in[8];
    const float* Wk_  = (const float*)d_in[9];
    const float* Wv_  = (const float*)d_in[10];
    const float* Wout = (const float*)d_in[11];
    const float* Wx2h = (const float*)d_in[12];
    const float* Wh2h = (const float*)d_in[13];
    float* out = (float*)d_out;

    cudaFuncSetAttribute(k1a_kv,   cudaFuncAttributeMaxDynamicSharedMemorySize, 51200);
    cudaFuncSetAttribute(k1a_ql,   cudaFuncAttributeMaxDynamicSharedMemorySize, 43008);
    cudaFuncSetAttribute(k2_gru,   cudaFuncAttributeMaxDynamicSharedMemorySize, 51200);
    cudaFuncSetAttribute(k3b_v2qk, cudaFuncAttributeMaxDynamicSharedMemorySize, 55296);
    cudaFuncSetAttribute(k3d_out,  cudaFuncAttributeMaxDynamicSharedMemorySize, 55296);

    k1a_kv   <<<128, 256, 51200>>>(x1, x2, Wkey, Wval);
    k1a_ql   <<<dim3(64, 8), 256, 43008>>>(hs, Wq);
    k1b_gate <<<BSZ / 8, 256>>>(bkey, bval);
    k2_gru   <<<dim3(64, 16, NBLK), 256, 51200>>>(hs, Wx2h, Wh2h);
    k3b_v2qk <<<dim3(64, 17, NBLK), 256, 55296>>>(Wv_, Wq_, Wk_);
    k3c_ctx  <<<BSZ, 256>>>();
    k3d_out  <<<dim3(64, 4, NBLK), 256, 55296>>>(Wout, hs, out);
}

// round 9
// speedup vs baseline: 1.3305x; 1.3305x over previous
#include <cuda_runtime.h>
#include <cuda_bf16.h>
#include <math.h>
#include <stdint.h>

#define BSZ   8192
#define NBLK  8
#define HDIM  256
#define KACT  4

typedef unsigned short u16;

// ---------------- device scratch ----------------
__device__ float g_mask  [BSZ * NBLK];
__device__ float g_hsnew [BSZ * NBLK * HDIM];
__device__ float g_q2    [BSZ * NBLK * 32];
__device__ float g_k2    [BSZ * NBLK * 32];
__device__ float g_v2    [BSZ * NBLK * 1024];
__device__ float g_kv    [BSZ * 2 * 48];
__device__ float g_ql    [BSZ * NBLK * 16];
// bf16 scratch
__device__ u16 g_hs_b    [BSZ * NBLK * HDIM];        // hs
__device__ u16 g_in_b    [BSZ * NBLK * 32];          // inputs
__device__ u16 g_hsn_b   [BSZ * NBLK * HDIM];        // hs_new
__device__ u16 g_ctx_b   [BSZ * NBLK * 1024];        // ctx
__device__ u16 g_WvT     [8 * 1024 * 256];           // [n][col][k]
__device__ u16 g_WoutT   [8 * 256 * 1024];
__device__ u16 g_Wh2hT   [8 * 768 * 256];
__device__ u16 g_Wx2hT   [8 * 768 * 32];
__device__ u16 g_WqkT    [8 * 64 * 256];

// ---------------- helpers ----------------
__device__ __forceinline__ uint32_t smem_u32(const void* p) {
    uint32_t a;
    asm("{ .reg .u64 t; cvta.to.shared.u64 t, %1; cvt.u32.u64 %0, t; }" : "=r"(a) : "l"(p));
    return a;
}
#define CPA16(dst, src) asm volatile("cp.async.cg.shared.global [%0], [%1], 16;" :: "r"(dst), "l"(src))
#define CPCOMMIT()      asm volatile("cp.async.commit_group;" ::: "memory")
#define CPWAIT1()       asm volatile("cp.async.wait_group 1;" ::: "memory")
#define CPWAIT0()       asm volatile("cp.async.wait_group 0;" ::: "memory")

__device__ __forceinline__ void mma8(float* d, uint32_t a0, uint32_t a1, uint32_t a2,
                                     uint32_t a3, uint32_t b0, uint32_t b1) {
    asm volatile("mma.sync.aligned.m16n8k8.row.col.f32.tf32.tf32.f32 "
        "{%0,%1,%2,%3}, {%4,%5,%6,%7}, {%8,%9}, {%0,%1,%2,%3};"
        : "+f"(d[0]), "+f"(d[1]), "+f"(d[2]), "+f"(d[3])
        : "r"(a0), "r"(a1), "r"(a2), "r"(a3), "r"(b0), "r"(b1));
}
__device__ __forceinline__ void mmabf(float* d, uint32_t a0, uint32_t a1, uint32_t a2,
                                      uint32_t a3, uint32_t b0, uint32_t b1) {
    asm volatile("mma.sync.aligned.m16n8k16.row.col.f32.bf16.bf16.f32 "
        "{%0,%1,%2,%3}, {%4,%5,%6,%7}, {%8,%9}, {%0,%1,%2,%3};"
        : "+f"(d[0]), "+f"(d[1]), "+f"(d[2]), "+f"(d[3])
        : "r"(a0), "r"(a1), "r"(a2), "r"(a3), "r"(b0), "r"(b1));
}
__device__ __forceinline__ float sigf(float x) { return 1.f / (1.f + expf(-x)); }
__device__ __forceinline__ uint32_t fu(float x) { return __float_as_uint(x); }
__device__ __forceinline__ u16 bf(float x) {
    __nv_bfloat16 h = __float2bfloat16_rn(x);
    return *(u16*)&h;
}
__device__ __forceinline__ uint32_t bf2(float x, float y) {
    __nv_bfloat162 h = __floats2bfloat162_rn(x, y);
    return *(uint32_t*)&h;
}
__device__ __forceinline__ uint32_t ld32b(const u16* p) { return *(const uint32_t*)p; }

// bf16 32x32-warp-tile step: A[row][k] stride 40, B[col][k] stride 40, K=32
#define MMA_BF32(A_, B_) \
    _Pragma("unroll") for (int ks = 0; ks < 2; ks++) { \
        int k0 = ks * 16 + 2 * lc; \
        uint32_t a[2][4]; \
        _Pragma("unroll") for (int mi = 0; mi < 2; mi++) { \
            const u16* ap = (A_) + (wm * 32 + mi * 16 + lr) * 40 + k0; \
            a[mi][0] = ld32b(ap);      a[mi][1] = ld32b(ap + 320); \
            a[mi][2] = ld32b(ap + 8);  a[mi][3] = ld32b(ap + 328); } \
        _Pragma("unroll") for (int ni = 0; ni < 4; ni++) { \
            const u16* bp = (B_) + (wn * 32 + ni * 8 + lr) * 40 + k0; \
            uint32_t b0f = ld32b(bp), b1f = ld32b(bp + 8); \
            mmabf(acc[0][ni], a[0][0], a[0][1], a[0][2], a[0][3], b0f, b1f); \
            mmabf(acc[1][ni], a[1][0], a[1][1], a[1][2], a[1][3], b0f, b1f); } }

// ================= prep: bf16 conversions + weight transposes ============
__global__ __launch_bounds__(256) void prep(
    const float* __restrict__ hs, const float* __restrict__ Wv_,
    const float* __restrict__ Wout, const float* __restrict__ Wh2h,
    const float* __restrict__ Wx2h, const float* __restrict__ Wq_,
    const float* __restrict__ Wk_)
{
    const int t = blockIdx.x * 256 + threadIdx.x;   // 0 .. 2,097,151
    const int seg = blockIdx.y;
    if (seg == 0) {
        const float4* s = (const float4*)hs;
        #pragma unroll
        for (int i = 0; i < 2; i++) {
            int i4 = t * 2 + i;
            float4 v = s[i4];
            uint2 o; o.x = bf2(v.x, v.y); o.y = bf2(v.z, v.w);
            *(uint2*)(g_hs_b + i4 * 4) = o;
        }
    } else if (seg == 1) {
        int k = t & 255, colp = t >> 8;
        int n = colp >> 10, col = colp & 1023;
        g_WvT[t] = bf(Wv_[(n * 256 + k) * 1024 + col]);
    } else if (seg == 2) {
        int k = t & 1023, colp = t >> 10;
        int n = colp >> 8, col = colp & 255;
        g_WoutT[t] = bf(Wout[(n * 1024 + k) * 256 + col]);
    } else if (seg == 3) {
        if (t < 1572864) {
            int k = t & 255, colp = t >> 8;
            int n = colp / 768, col = colp % 768;
            g_Wh2hT[t] = bf(Wh2h[(n * 256 + k) * 768 + col]);
        }
    } else {
        if (t < 196608) {
            int k = t & 31, colp = t >> 5;
            int n = colp / 768, col = colp % 768;
            g_Wx2hT[t] = bf(Wx2h[(n * 32 + k) * 768 + col]);
        } else if (t < 196608 + 131072) {
            int u = t - 196608;
            int k = u & 255, colp = u >> 8;
            int n = colp >> 6, c = colp & 63;
            g_WqkT[u] = bf((c < 32) ? Wq_[(n * 256 + k) * 32 + c]
                                    : Wk_[(n * 256 + k) * 32 + c - 32]);
        }
    }
}

// ================= k1a_kv: [kL|vL] = x @ [Wkey|Wval] (tf32, unchanged) ===
__global__ __launch_bounds__(256) void k1a_kv(
    const float* __restrict__ x1, const float* __restrict__ x2,
    const float* __restrict__ Wkey, const float* __restrict__ Wval)
{
    extern __shared__ float sm[];
    float* sA = sm;
    float* sB = sm + 2 * 4608;
    uint32_t aB = smem_u32(sA), bB = smem_u32(sB);
    const int b0 = blockIdx.x * 128;
    const int tid = threadIdx.x, warp = tid >> 5, lane = tid & 31;
    const int wm = warp >> 1, wn = warp & 1;
    const int lr = lane >> 2, lc = lane & 3;
    float acc[2][3][4] = {};

#define KV_ISSUE(kt, st) { \
    for (int l = tid; l < 1024; l += 256) { int r = l >> 3, k4 = l & 7; \
        int row = b0 + r; const float* src = ((row & 1) ? x2 : x1) + (row >> 1) * 256 + (kt) * 32 + k4 * 4; \
        CPA16(aB + ((st) * 4608 + r * 36 + k4 * 4) * 4, src); } \
    for (int l = tid; l < 384; l += 256) { int k = l / 12, c4 = l % 12; int c = c4 * 4; \
        const float* src = (c < 16) ? &Wkey[((kt) * 32 + k) * 16 + c] : &Wval[((kt) * 32 + k) * 32 + c - 16]; \
        CPA16(bB + ((st) * 1792 + k * 56 + c) * 4, src); } \
    CPCOMMIT(); }

    KV_ISSUE(0, 0);
    for (int kt = 0; kt < 8; kt++) {
        if (kt < 7) { KV_ISSUE(kt + 1, (kt + 1) & 1); CPWAIT1(); }
        else CPWAIT0();
        __syncthreads();
        const float* A_ = sA + (kt & 1) * 4608;
        const float* B_ = sB + (kt & 1) * 1792;
        #pragma unroll
        for (int ks = 0; ks < 4; ks++) {
            int k0 = ks * 8;
            uint32_t a[2][4];
            #pragma unroll
            for (int mi = 0; mi < 2; mi++) {
                const float* ap = &A_[(wm * 32 + mi * 16 + lr) * 36 + k0 + lc];
                a[mi][0] = fu(ap[0]); a[mi][1] = fu(ap[288]);
                a[mi][2] = fu(ap[4]); a[mi][3] = fu(ap[292]);
            }
            #pragma unroll
            for (int ni = 0; ni < 3; ni++) {
                int col = wn * 24 + ni * 8 + lr;
                uint32_t b0f = fu(B_[(k0 + lc) * 56 + col]);
                uint32_t b1f = fu(B_[(k0 + lc + 4) * 56 + col]);
                mma8(acc[0][ni], a[0][0], a[0][1], a[0][2], a[0][3], b0f, b1f);
                mma8(acc[1][ni], a[1][0], a[1][1], a[1][2], a[1][3], b0f, b1f);
            }
        }
        __syncthreads();
    }
    #pragma unroll
    for (int mi = 0; mi < 2; mi++)
        #pragma unroll
        for (int ni = 0; ni < 3; ni++) {
            int col = wn * 24 + ni * 8 + 2 * lc;
            int r0 = b0 + wm * 32 + mi * 16 + lr;
            *(float2*)&g_kv[r0 * 48 + col]       = make_float2(acc[mi][ni][0], acc[mi][ni][1]);
            *(float2*)&g_kv[(r0 + 8) * 48 + col] = make_float2(acc[mi][ni][2], acc[mi][ni][3]);
        }
}

// ================= k1a_ql: qL = hs @ Wq[n] (tf32, unchanged) =============
__global__ __launch_bounds__(256) void k1a_ql(
    const float* __restrict__ hs, const float* __restrict__ Wq)
{
    extern __shared__ float sm[];
    float* sA = sm;
    float* sB = sm + 2 * 4608;
    uint32_t aB = smem_u32(sA), bB = smem_u32(sB);
    const int n = blockIdx.y, b0 = blockIdx.x * 128;
    const int tid = threadIdx.x, warp = tid >> 5, lane = tid & 31;
    const int wm = warp;
    const int lr = lane >> 2, lc = lane & 3;
    float acc[2][4] = {};

#define QL_ISSUE(kt, st) { \
    for (int l = tid; l < 1024; l += 256) { int r = l >> 3, k4 = l & 7; \
        CPA16(aB + ((st) * 4608 + r * 36 + k4 * 4) * 4, \
              &hs[((b0 + r) * NBLK + n) * 256 + (kt) * 32 + k4 * 4]); } \
    for (int l = tid; l < 128; l += 256) { int k = l >> 2, c4 = l & 3; \
        CPA16(bB + ((st) * 768 + k * 24 + c4 * 4) * 4, \
              &Wq[(n * 256 + (kt) * 32 + k) * 16 + c4 * 4]); } \
    CPCOMMIT(); }

    QL_ISSUE(0, 0);
    for (int kt = 0; kt < 8; kt++) {
        if (kt < 7) { QL_ISSUE(kt + 1, (kt + 1) & 1); CPWAIT1(); }
        else CPWAIT0();
        __syncthreads();
        const float* A_ = sA + (kt & 1) * 4608;
        const float* B_ = sB + (kt & 1) * 768;
        #pragma unroll
        for (int ks = 0; ks < 4; ks++) {
            int k0 = ks * 8;
            const float* ap = &A_[(wm * 16 + lr) * 36 + k0 + lc];
            uint32_t a0 = fu(ap[0]), a1 = fu(ap[288]), a2 = fu(ap[4]), a3 = fu(ap[292]);
            #pragma unroll
            for (int ni = 0; ni < 2; ni++) {
                int col = ni * 8 + lr;
                uint32_t b0f = fu(B_[(k0 + lc) * 24 + col]);
                uint32_t b1f = fu(B_[(k0 + lc + 4) * 24 + col]);
                mma8(acc[ni], a0, a1, a2, a3, b0f, b1f);
            }
        }
        __syncthreads();
    }
    #pragma unroll
    for (int ni = 0; ni < 2; ni++) {
        int col = ni * 8 + 2 * lc;
        int r0 = b0 + wm * 16 + lr;
        *(float2*)&g_ql[(r0 * NBLK + n) * 16 + col]       = make_float2(acc[ni][0], acc[ni][1]);
        *(float2*)&g_ql[((r0 + 8) * NBLK + n) * 16 + col] = make_float2(acc[ni][2], acc[ni][3]);
    }
}

// ================= k1b: scores, top-k mask, softmax, inputs(bf16) ========
__global__ __launch_bounds__(256) void k1b_gate(
    const float* __restrict__ bkey, const float* __restrict__ bval)
{
    const int w = threadIdx.x >> 5, lane = threadIdx.x & 31;
    const int b = blockIdx.x * 8 + w;

    __shared__ float sKL[8][48];
    __shared__ float sVL[8][96];
    __shared__ float sQL[8][128];
    __shared__ float sS [8][24];
    __shared__ float sM [8][8];

    for (int o = lane; o < 48; o += 32) {
        int s = o >> 4, j = o & 15;
        sKL[w][o] = bkey[j] + (s < 2 ? g_kv[(b * 2 + s) * 48 + j] : 0.f);
    }
    for (int o = lane; o < 96; o += 32) {
        int s = o >> 5, j = o & 31;
        sVL[w][o] = bval[j] + (s < 2 ? g_kv[(b * 2 + s) * 48 + 16 + j] : 0.f);
    }
    for (int o = lane; o < 128; o += 32) sQL[w][o] = g_ql[b * 128 + o];
    __syncwarp();

    for (int o = lane; o < 24; o += 32) {
        int nn = o / 3, s = o % 3;
        float acc = 0.f;
        #pragma unroll
        for (int j = 0; j < 16; j++) acc += sQL[w][nn * 16 + j] * sKL[w][s * 16 + j];
        sS[w][o] = acc * 0.25f;
    }
    __syncwarp();

    if (lane < 8) {
        float nu = sS[w][lane * 3 + 2];
        int rank = 0;
        #pragma unroll
        for (int n2 = 0; n2 < 8; n2++) {
            float nu2 = sS[w][n2 * 3 + 2];
            rank += (nu2 > nu) || (nu2 == nu && n2 < lane);
        }
        float m = (rank < (NBLK - KACT)) ? 0.f : 1.f;
        sM[w][lane] = m;
        g_mask[b * NBLK + lane] = m;
    }
    __syncwarp();

    for (int o = lane; o < 256; o += 32) {
        int nn = o >> 5, j = o & 31;
        float s0 = sS[w][nn * 3 + 0], s1 = sS[w][nn * 3 + 1], s2 = sS[w][nn * 3 + 2];
        float mx = fmaxf(s0, fmaxf(s1, s2));
        float e0 = expf(s0 - mx), e1 = expf(s1 - mx), e2 = expf(s2 - mx);
        float inv = 1.f / (e0 + e1 + e2);
        float val = (e0 * sVL[w][j] + e1 * sVL[w][32 + j] + e2 * sVL[w][64 + j])
                    * inv * sM[w][nn];
        g_in_b[(b * NBLK + nn) * 32 + j] = bf(val);
    }
}

// ================= k2: fused GRU (bf16 m16n8k16) ==========================
// grid (64, 16, 8); 128 rows x 16h x 3 gates. Static smem 28160B.
__global__ __launch_bounds__(256) void k2_gru(const float* __restrict__ hs)
{
    __shared__ u16 smem2[14080];
    u16* sA = smem2;               // 2 stages x 5120 u16 (128 x 40)
    u16* sB = smem2 + 10240;       // 2 stages x 1920 u16 (48 x 40)
    uint32_t aB = smem_u32(sA), bB = smem_u32(sB);
    const int n = blockIdx.z, b0 = blockIdx.x * 128, h0 = blockIdx.y * 16;
    const int tid = threadIdx.x, warp = tid >> 5, lane = tid & 31;
    const int wm = warp >> 1, wn = warp & 1;
    const int lr = lane >> 2, lc = lane & 3;

    float arz[2][2][4] = {};
    float anx[2][4] = {};
    float anh[2][4] = {};

#define K2_MMAB(A_, B_, NACC) \
    _Pragma("unroll") for (int ks = 0; ks < 2; ks++) { \
        int k0 = ks * 16 + 2 * lc; \
        uint32_t a[2][4]; \
        _Pragma("unroll") for (int mi = 0; mi < 2; mi++) { \
            const u16* ap = (A_) + (wm * 32 + mi * 16 + lr) * 40 + k0; \
            a[mi][0] = ld32b(ap);     a[mi][1] = ld32b(ap + 320); \
            a[mi][2] = ld32b(ap + 8); a[mi][3] = ld32b(ap + 328); } \
        _Pragma("unroll") for (int g = 0; g < 3; g++) { \
            const u16* bp = (B_) + (g * 16 + wn * 8 + lr) * 40 + k0; \
            uint32_t b0f = ld32b(bp), b1f = ld32b(bp + 8); \
            float* d0 = (g < 2) ? arz[0][g] : NACC[0]; \
            float* d1 = (g < 2) ? arz[1][g] : NACC[1]; \
            mmabf(d0, a[0][0], a[0][1], a[0][2], a[0][3], b0f, b1f); \
            mmabf(d1, a[1][0], a[1][1], a[1][2], a[1][3], b0f, b1f); } }

    // hoisted cp.async addressing: A = 2 chunks/thread, B = 1 (tid<192)
    const int rA = tid >> 2, chA = tid & 3;
    const u16* srcA0 = g_hs_b + ((b0 + rA) * NBLK + n) * 256 + chA * 8;
    const u16* srcA1 = g_hs_b + ((b0 + rA + 64) * NBLK + n) * 256 + chA * 8;
    const uint32_t dstA0 = aB + rA * 80 + chA * 16;
    const uint32_t dstA1 = aB + (rA + 64) * 80 + chA * 16;
    const int cB = tid >> 2, chB = tid & 3;
    const int gB = cB >> 4, ccB = cB & 15;
    const bool bOK = (tid < 192);
    const u16* srcBh = g_Wh2hT + (n * 768 + gB * 256 + h0 + ccB) * 256 + chB * 8;
    const u16* srcBx = g_Wx2hT + (n * 768 + gB * 256 + h0 + ccB) * 32 + chB * 8;
    const uint32_t dstBs = bB + cB * 80 + chB * 16;

#define K2_ISS(kt, st) { \
    CPA16(dstA0 + (st) * 10240, srcA0 + (kt) * 32); \
    CPA16(dstA1 + (st) * 10240, srcA1 + (kt) * 32); \
    if (bOK) CPA16(dstBs + (st) * 3840, srcBh + (kt) * 32); \
    CPCOMMIT(); }

    // phase 1: gate_x (K=32) into stage 0
    {
        const u16* sa0 = g_in_b + ((b0 + rA) * NBLK + n) * 32 + chA * 8;
        const u16* sa1 = g_in_b + ((b0 + rA + 64) * NBLK + n) * 32 + chA * 8;
        CPA16(dstA0, sa0);
        CPA16(dstA1, sa1);
        if (bOK) CPA16(dstBs, srcBx);
        CPCOMMIT(); CPWAIT0();
    }
    __syncthreads();
    K2_MMAB(sA, sB, anx);
    __syncthreads();

    // phase 2: gate_h (K=256, 8 tiles, double-buffered)
    K2_ISS(0, 0);
    for (int kt = 0; kt < 8; kt++) {
        if (kt < 7) { K2_ISS(kt + 1, (kt + 1) & 1); CPWAIT1(); }
        else CPWAIT0();
        __syncthreads();
        const u16* A_ = sA + (kt & 1) * 5120;
        const u16* B_ = sB + (kt & 1) * 1920;
        K2_MMAB(A_, B_, anh);
        __syncthreads();
    }

    // epilogue
    #pragma unroll
    for (int mi = 0; mi < 2; mi++)
        #pragma unroll
        for (int half = 0; half < 2; half++) {
            int row = b0 + wm * 32 + mi * 16 + lr + half * 8;
            int idx = (row * NBLK + n) * HDIM + h0 + wn * 8 + 2 * lc;
            float2 hold = *(const float2*)&hs[idx];
            int e = half * 2;
            float r0 = sigf(arz[mi][0][e + 0]);
            float r1 = sigf(arz[mi][0][e + 1]);
            float z0 = sigf(arz[mi][1][e + 0]);
            float z1 = sigf(arz[mi][1][e + 1]);
            float n0 = tanhf(anx[mi][e + 0] + r0 * anh[mi][e + 0]);
            float n1 = tanhf(anx[mi][e + 1] + r1 * anh[mi][e + 1]);
            float2 o;
            o.x = n0 + z0 * (hold.x - n0);
            o.y = n1 + z1 * (hold.y - n1);
            *(float2*)&g_hsnew[idx] = o;
            *(uint32_t*)&g_hsn_b[idx] = bf2(o.x, o.y);
        }
}

// ========== k3b fused (bf16): v2 = hsn @ Wv  AND  [q2|k2] = hsn @ [Wq|Wk]
// grid (64, 17, 8). Static smem 30720B.
__global__ __launch_bounds__(256) void k3b_v2qk()
{
    __shared__ u16 smem3[15360];
    u16* sA = smem3;               // 2 x 5120 (128 x 40)
    u16* sB = smem3 + 10240;       // 2 x 2560 (64 x 40)
    uint32_t aB = smem_u32(sA), bB = smem_u32(sB);
    const int n = blockIdx.z, b0 = blockIdx.x * 128;
    const int oy = blockIdx.y;
    const bool isqk = (oy == 16);
    const int o0 = oy * 64;
    const int tid = threadIdx.x, warp = tid >> 5, lane = tid & 31;
    const int wm = warp >> 1, wn = warp & 1;
    const int lr = lane >> 2, lc = lane & 3;
    float acc[2][4][4] = {};

    const int rA = tid >> 2, chA = tid & 3;
    const u16* srcA0 = g_hsn_b + ((b0 + rA) * NBLK + n) * 256 + chA * 8;
    const u16* srcA1 = g_hsn_b + ((b0 + rA + 64) * NBLK + n) * 256 + chA * 8;
    const uint32_t dstA0 = aB + rA * 80 + chA * 16;
    const uint32_t dstA1 = aB + (rA + 64) * 80 + chA * 16;
    const int cB = tid >> 2, chB = tid & 3;
    const u16* srcB = isqk ? (g_WqkT + (n * 64 + cB) * 256 + chB * 8)
                           : (g_WvT + (n * 1024 + o0 + cB) * 256 + chB * 8);
    const uint32_t dstB = bB + cB * 80 + chB * 16;

#define K3B_ISS(kt, st) { \
    CPA16(dstA0 + (st) * 10240, srcA0 + (kt) * 32); \
    CPA16(dstA1 + (st) * 10240, srcA1 + (kt) * 32); \
    CPA16(dstB + (st) * 5120, srcB + (kt) * 32); \
    CPCOMMIT(); }

    K3B_ISS(0, 0);
    for (int kt = 0; kt < 8; kt++) {
        if (kt < 7) { K3B_ISS(kt + 1, (kt + 1) & 1); CPWAIT1(); }
        else CPWAIT0();
        __syncthreads();
        const u16* A_ = sA + (kt & 1) * 5120;
        const u16* B_ = sB + (kt & 1) * 2560;
        MMA_BF32(A_, B_);
        __syncthreads();
    }
    if (!isqk) {
        #pragma unroll
        for (int mi = 0; mi < 2; mi++)
            #pragma unroll
            for (int ni = 0; ni < 4; ni++) {
                int col = o0 + wn * 32 + ni * 8 + 2 * lc;
                int r0 = b0 + wm * 32 + mi * 16 + lr;
                *(float2*)&g_v2[(r0 * NBLK + n) * 1024 + col]       = make_float2(acc[mi][ni][0], acc[mi][ni][1]);
                *(float2*)&g_v2[((r0 + 8) * NBLK + n) * 1024 + col] = make_float2(acc[mi][ni][2], acc[mi][ni][3]);
            }
    } else {
        #pragma unroll
        for (int mi = 0; mi < 2; mi++)
            #pragma unroll
            for (int ni = 0; ni < 4; ni++) {
                int col = wn * 32 + ni * 8 + 2 * lc;
                float* dst = (col < 32) ? g_q2 : g_k2;
                int cc = col & 31;
                int r0 = b0 + wm * 32 + mi * 16 + lr;
                *(float2*)&dst[(r0 * NBLK + n) * 32 + cc]       = make_float2(acc[mi][ni][0], acc[mi][ni][1]);
                *(float2*)&dst[((r0 + 8) * NBLK + n) * 32 + cc] = make_float2(acc[mi][ni][2], acc[mi][ni][3]);
            }
    }
}

// ================= k3c: fused attention + ctx = att @ v2 (ctx -> bf16) ===
__global__ __launch_bounds__(256) void k3c_ctx()
{
    const int b = blockIdx.x;
    __shared__ float4 sV[2048];
    __shared__ float sQ[256], sK[256], sAtt[256];

    const float4* vb = (const float4*)(g_v2 + b * 8192);
    for (int l = threadIdx.x; l < 2048; l += 256) sV[l] = vb[l];
    sQ[threadIdx.x] = g_q2[b * 256 + threadIdx.x];
    sK[threadIdx.x] = g_k2[b * 256 + threadIdx.x];
    __syncthreads();

    if (threadIdx.x < 32) {
        const int lane = threadIdx.x;
        const int h = lane >> 3, nq = lane & 7;
        float sc[8], mx = -1e30f;
        #pragma unroll
        for (int m = 0; m < 8; m++) {
            float s = 0.f;
            #pragma unroll
            for (int dk = 0; dk < 8; dk++)
                s += sQ[nq * 32 + h * 8 + dk] * sK[m * 32 + h * 8 + dk];
            s *= 0.35355339059327373f;
            sc[m] = s;
            mx = fmaxf(mx, s);
        }
        float den = 0.f;
        #pragma unroll
        for (int m = 0; m < 8; m++) { sc[m] = expf(sc[m] - mx); den += sc[m]; }
        float scale = g_mask[b * NBLK + nq] / den;
        #pragma unroll
        for (int m = 0; m < 8; m++)
            sAtt[(h * 8 + nq) * 8 + m] = sc[m] * scale;
    }
    __syncthreads();

    u16* cb = g_ctx_b + b * 8192;
    for (int l = threadIdx.x; l < 2048; l += 256) {
        int nq = l >> 8, c4 = l & 255, g = c4 >> 6;
        const float* ap = &sAtt[(g * 8 + nq) * 8];
        float4 acc = make_float4(0.f, 0.f, 0.f, 0.f);
        #pragma unroll
        for (int m = 0; m < 8; m++) {
            float a = ap[m];
            float4 v = sV[m * 256 + c4];
            acc.x += a * v.x; acc.y += a * v.y; acc.z += a * v.z; acc.w += a * v.w;
        }
        uint2 o; o.x = bf2(acc.x, acc.y); o.y = bf2(acc.z, acc.w);
        *(uint2*)(cb + l * 4) = o;
    }
}

// ================= k3d (bf16): out = mask*(ctx@Wout + hsn) + (1-m)*hs ====
__global__ __launch_bounds__(256) void k3d_out(
    const float* __restrict__ hs, float* __restrict__ out)
{
    __shared__ u16 smem4[15360];
    u16* sA = smem4;
    u16* sB = smem4 + 10240;
    uint32_t aB = smem_u32(sA), bB = smem_u32(sB);
    const int n = blockIdx.z, b0 = blockIdx.x * 128, o0 = blockIdx.y * 64;
    const int tid = threadIdx.x, warp = tid >> 5, lane = tid & 31;
    const int wm = warp >> 1, wn = warp & 1;
    const int lr = lane >> 2, lc = lane & 3;
    float acc[2][4][4] = {};

    const int rA = tid >> 2, chA = tid & 3;
    const u16* srcA0 = g_ctx_b + ((b0 + rA) * NBLK + n) * 1024 + chA * 8;
    const u16* srcA1 = g_ctx_b + ((b0 + rA + 64) * NBLK + n) * 1024 + chA * 8;
    const uint32_t dstA0 = aB + rA * 80 + chA * 16;
    const uint32_t dstA1 = aB + (rA + 64) * 80 + chA * 16;
    const int cB = tid >> 2, chB = tid & 3;
    const u16* srcB = g_WoutT + (n * 256 + o0 + cB) * 1024 + chB * 8;
    const uint32_t dstB = bB + cB * 80 + chB * 16;

#define K3D_ISS(kt, st) { \
    CPA16(dstA0 + (st) * 10240, srcA0 + (kt) * 32); \
    CPA16(dstA1 + (st) * 10240, srcA1 + (kt) * 32); \
    CPA16(dstB + (st) * 5120, srcB + (kt) * 32); \
    CPCOMMIT(); }

    K3D_ISS(0, 0);
    for (int kt = 0; kt < 32; kt++) {
        if (kt < 31) { K3D_ISS(kt + 1, (kt + 1) & 1); CPWAIT1(); }
        else CPWAIT0();
        __syncthreads();
        const u16* A_ = sA + (kt & 1) * 5120;
        const u16* B_ = sB + (kt & 1) * 2560;
        MMA_BF32(A_, B_);
        __syncthreads();
    }
    #pragma unroll
    for (int mi = 0; mi < 2; mi++)
        #pragma unroll
        for (int ni = 0; ni < 4; ni++) {
            int col = o0 + wn * 32 + ni * 8 + 2 * lc;
            #pragma unroll
            for (int half = 0; half < 2; half++) {
                int row = b0 + wm * 32 + mi * 16 + lr + half * 8;
                float m = g_mask[row * NBLK + n];
                int idx = (row * NBLK + n) * HDIM + col;
                float2 hn = *(const float2*)&g_hsnew[idx];
                float2 ho = *(const float2*)&hs[idx];
                float2 r;
                r.x = m * (acc[mi][ni][half * 2]     + hn.x) + (1.f - m) * ho.x;
                r.y = m * (acc[mi][ni][half * 2 + 1] + hn.y) + (1.f - m) * ho.y;
                *(float2*)&out[idx] = r;
            }
        }
}

// =========================== launch ======================================
extern "C" void kernel_launch(void* const* d_in, const int* in_sizes, int n_in,
                              void* d_out, int out_size)
{
    const float* x1   = (const float*)d_in[0];
    const float* x2   = (const float*)d_in[1];
    const float* hs   = (const float*)d_in[2];
    const float* Wkey = (const float*)d_in[3];
    const float* bkey = (const float*)d_in[4];
    const float* Wval = (const float*)d_in[5];
    const float* bval = (const float*)d_in[6];
    const float* Wq   = (const float*)d_in[7];
    const float* Wq_  = (const float*)d_in[8];
    const float* Wk_  = (const float*)d_in[9];
    const float* Wv_  = (const float*)d_in[10];
    const float* Wout = (const float*)d_in[11];
    const float* Wx2h = (const float*)d_in[12];
    const float* Wh2h = (const float*)d_in[13];
    float* out = (float*)d_out;

    cudaFuncSetAttribute(k1a_kv, cudaFuncAttributeMaxDynamicSharedMemorySize, 51200);
    cudaFuncSetAttribute(k1a_ql, cudaFuncAttributeMaxDynamicSharedMemorySize, 43008);

    prep     <<<dim3(8192, 5), 256>>>(hs, Wv_, Wout, Wh2h, Wx2h, Wq_, Wk_);
    k1a_kv   <<<128, 256, 51200>>>(x1, x2, Wkey, Wval);
    k1a_ql   <<<dim3(64, 8), 256, 43008>>>(hs, Wq);
    k1b_gate <<<BSZ / 8, 256>>>(bkey, bval);
    k2_gru   <<<dim3(64, 16, NBLK), 256>>>(hs);
    k3b_v2qk <<<dim3(64, 17, NBLK), 256>>>();
    k3c_ctx  <<<BSZ, 256>>>();
    k3d_out  <<<dim3(64, 4, NBLK), 256>>>(hs, out);
}